// round 5
// baseline (speedup 1.0000x reference)
#include <cuda_runtime.h>
#include <cuda_fp16.h>
#include <math.h>
#include <stdint.h>

// ---------------- problem constants ----------------
#define B_    32
#define L_    12
#define N_    512
#define D_    128
#define BN_   16384      // B_*N_
#define LBN_  196608     // L_*BN_
#define FK_   256
#define T_    12
#define RES_ELEMS  25165824ULL   // 32*12*512*128
#define FORE_ELEMS 50331648ULL

// ---------------- device scratch (static, no allocations) ----------------
__device__ float  g_GI    [(size_t)LBN_ * 384];
__device__ float  g_rnn   [(size_t)LBN_ * 128];
__device__ float  g_rnnpe [(size_t)LBN_ * 128];
__device__ float  g_QKV   [(size_t)LBN_ * 384];
__device__ float  g_attn  [(size_t)LBN_ * 128];
__device__ float  g_Z0    [(size_t)LBN_ * 128];
__device__ __half g_Kc    [(size_t)23 * BN_ * 128];
__device__ __half g_Vc    [(size_t)23 * BN_ * 128];
__device__ float  g_pred  [(size_t)T_ * BN_ * 128];
__device__ float  g_aresT [(size_t)11 * BN_ * 128];
__device__ float  g_Qbuf  [(size_t)BN_ * 128];
__device__ float  g_GIdec [(size_t)BN_ * 384];
__device__ float  g_g     [(size_t)BN_ * 128];
__device__ float  g_hlast [(size_t)BN_ * 128];
__device__ float  g_pe    [64 * 128];
__device__ float  g_Kpe   [24 * 128];
__device__ float  g_Vpe   [24 * 128];
// pre-rounded (tf32) weights
__device__ float g_wih_r  [49152];
__device__ float g_whh_r  [49152];
__device__ float g_inw_r  [49152];
__device__ float g_outw_r [16384];
__device__ float g_backw_r[16384];
__device__ float g_forew_r[32768];
__device__ float g_Wf     [49152];
__device__ float g_bf     [384];

// ---------------- helpers ----------------
__device__ __forceinline__ float rnd_tf32(float x) {
    unsigned u;
    asm("cvt.rna.tf32.f32 %0, %1;" : "=r"(u) : "f"(x));
    return __uint_as_float(u);
}
__device__ __forceinline__ void mma1688(float c[4], const unsigned a[4], const unsigned b[2]) {
    asm volatile(
        "mma.sync.aligned.m16n8k8.row.col.f32.tf32.tf32.f32 "
        "{%0,%1,%2,%3}, {%4,%5,%6,%7}, {%8,%9}, {%0,%1,%2,%3};\n"
        : "+f"(c[0]), "+f"(c[1]), "+f"(c[2]), "+f"(c[3])
        : "r"(a[0]), "r"(a[1]), "r"(a[2]), "r"(a[3]), "r"(b[0]), "r"(b[1]));
}
__device__ __forceinline__ float sigmoid_f(float x) {
    return __fdividef(1.f, 1.f + __expf(-x));
}
__device__ __forceinline__ float tanh_f(float x) {
    float ex = __expf(2.f * x);
    return 1.f - __fdividef(2.f, ex + 1.f);
}

#define CP16(dst, src) asm volatile("cp.async.cg.shared.global [%0], [%1], 16;" :: "r"(dst), "l"(src))

// ---------------- templated tf32 GEMM: cp.async 3-stage ----------------
// C[M,N] = A[M,128] @ W[N,128]^T + bias ; W pre-rounded tf32.
// MODE 0: plain. 1: plain + tf32-rounded out. 2: forecast permute (N=256).
// 3: QKV full write + scatter cols[128,384) -> fp16 Kc/Vc at row index (N=384).
// 4: proj: cols[0,128)->C stride128, cols[128,384) -> fp16 Kc/Vc at pos (N=384).
// 5: like 1 (N=128) + rows>=11*BN also copied to extra (pred[0]).
// 6: backcast+LN fused (N=128).
// APERM 1: A row remap (l*BN+b*512+n) -> X row (b*12+l)*512+n.
#define GSMEM_WORDS (2 * 3 * 2560)
#define GSMEM_BYTES (GSMEM_WORDS * 4)

template <int MODE, int APERM>
__global__ __launch_bounds__(256, 2) void gemm3(
    const float* __restrict__ A, const float* __restrict__ W,
    const float* __restrict__ bias, float* __restrict__ C,
    int M, int N, int pos,
    __half* __restrict__ Kc, __half* __restrict__ Vc,
    float* __restrict__ extra,
    const float* __restrict__ Xg, const float* __restrict__ gammap,
    const float* __restrict__ betap)
{
    extern __shared__ float sm[];

    const int tid = threadIdx.x, lane = tid & 31, warp = tid >> 5;
    const int wm = (warp >> 2) * 64;
    const int wn = (warp & 3) * 32;
    const int blockM = blockIdx.y * 128;
    const int blockN = blockIdx.x * 128;

    const int arow = tid >> 1;
    const int koff = (tid & 1) * 8;
    const float* Ag;
    if (APERM) {
        int grow = blockM + arow;
        int l = grow >> 14, rem = grow & 16383, b = rem >> 9, n = rem & 511;
        Ag = A + (((size_t)(b * 12 + l) * 512 + n) << 7) + koff;
    } else {
        Ag = A + (size_t)(blockM + arow) * 128 + koff;
    }
    const float* Wg = W + (size_t)(blockN + arow) * 128 + koff;
    uint32_t smb = (uint32_t)__cvta_generic_to_shared(sm);
    uint32_t a_s0 = smb + (uint32_t)(arow * 20 + koff) * 4;
    uint32_t w_s0 = smb + (uint32_t)(7680 + arow * 20 + koff) * 4;

    #define LOADSTAGE(S, KB) do { \
        uint32_t as_ = a_s0 + (S) * 2560u * 4u; const float* ag_ = Ag + (KB); \
        CP16(as_, ag_); CP16(as_ + 16, ag_ + 4); \
        uint32_t ws_ = w_s0 + (S) * 2560u * 4u; const float* wg_ = Wg + (KB); \
        CP16(ws_, wg_); CP16(ws_ + 16, wg_ + 4); \
    } while (0)

    float c[4][4][4];
    #pragma unroll
    for (int i = 0; i < 4; i++)
        #pragma unroll
        for (int j = 0; j < 4; j++)
            #pragma unroll
            for (int r = 0; r < 4; r++) c[i][j][r] = 0.f;

    LOADSTAGE(0, 0);
    asm volatile("cp.async.commit_group;");
    LOADSTAGE(1, 16);
    asm volatile("cp.async.commit_group;");

    #pragma unroll
    for (int it = 0; it < 8; ++it) {
        asm volatile("cp.async.wait_group 1;");
        __syncthreads();
        if (it + 2 < 8) LOADSTAGE((it + 2) % 3, (it + 2) * 16);
        asm volatile("cp.async.commit_group;");

        const float* Ab = sm + (it % 3) * 2560;
        const float* Wb = sm + 7680 + (it % 3) * 2560;
        #pragma unroll
        for (int ks = 0; ks < 16; ks += 8) {
            unsigned af[4][4], bf_[4][2];
            const int kc = ks + (lane & 3);
            #pragma unroll
            for (int mt = 0; mt < 4; mt++) {
                int row = wm + mt * 16 + (lane >> 2);
                af[mt][0] = __float_as_uint(Ab[row * 20 + kc]);
                af[mt][1] = __float_as_uint(Ab[(row + 8) * 20 + kc]);
                af[mt][2] = __float_as_uint(Ab[row * 20 + kc + 4]);
                af[mt][3] = __float_as_uint(Ab[(row + 8) * 20 + kc + 4]);
            }
            #pragma unroll
            for (int nt = 0; nt < 4; nt++) {
                int col = wn + nt * 8 + (lane >> 2);
                bf_[nt][0] = __float_as_uint(Wb[col * 20 + kc]);
                bf_[nt][1] = __float_as_uint(Wb[col * 20 + kc + 4]);
            }
            #pragma unroll
            for (int mt = 0; mt < 4; mt++)
                #pragma unroll
                for (int nt = 0; nt < 4; nt++)
                    mma1688(c[mt][nt], af[mt], bf_[nt]);
        }
    }
    #undef LOADSTAGE

    // ================= epilogues =================
    if (MODE == 6) {
        asm volatile("cp.async.wait_group 0;");
        __syncthreads();
        float* ssum = sm;
        float* ssq  = sm + 512;
        float ps[8], pq[8];
        #pragma unroll
        for (int p = 0; p < 8; p++) { ps[p] = 0.f; pq[p] = 0.f; }
        size_t xr[8];
        #pragma unroll
        for (int mt = 0; mt < 4; mt++) {
            int gr0 = blockM + wm + mt * 16 + (lane >> 2);
            int gr1 = gr0 + 8;
            int l0 = gr0 >> 14, r0 = gr0 & 16383;
            xr[mt * 2]     = (((size_t)((r0 >> 9) * 12 + l0) * 512 + (r0 & 511)) << 7);
            int l1 = gr1 >> 14, r1 = gr1 & 16383;
            xr[mt * 2 + 1] = (((size_t)((r1 >> 9) * 12 + l1) * 512 + (r1 & 511)) << 7);
            #pragma unroll
            for (int nt = 0; nt < 4; nt++) {
                int gc = wn + nt * 8 + 2 * (lane & 3);
                float bv0 = bias[gc], bv1 = bias[gc + 1];
                float u00 = Xg[xr[mt*2]   + gc]     - fmaxf(c[mt][nt][0] + bv0, 0.f);
                float u01 = Xg[xr[mt*2]   + gc + 1] - fmaxf(c[mt][nt][1] + bv1, 0.f);
                float u10 = Xg[xr[mt*2+1] + gc]     - fmaxf(c[mt][nt][2] + bv0, 0.f);
                float u11 = Xg[xr[mt*2+1] + gc + 1] - fmaxf(c[mt][nt][3] + bv1, 0.f);
                c[mt][nt][0] = u00; c[mt][nt][1] = u01;
                c[mt][nt][2] = u10; c[mt][nt][3] = u11;
                ps[mt*2]   += u00 + u01;  pq[mt*2]   += u00*u00 + u01*u01;
                ps[mt*2+1] += u10 + u11;  pq[mt*2+1] += u10*u10 + u11*u11;
            }
        }
        #pragma unroll
        for (int o = 1; o < 4; o <<= 1) {
            #pragma unroll
            for (int p = 0; p < 8; p++) {
                ps[p] += __shfl_xor_sync(0xffffffffu, ps[p], o);
                pq[p] += __shfl_xor_sync(0xffffffffu, pq[p], o);
            }
        }
        int wnIdx = warp & 3;
        if ((lane & 3) == 0) {
            #pragma unroll
            for (int mt = 0; mt < 4; mt++) {
                int lr = wm + mt * 16 + (lane >> 2);
                ssum[wnIdx * 128 + lr]     = ps[mt*2];
                ssq [wnIdx * 128 + lr]     = pq[mt*2];
                ssum[wnIdx * 128 + lr + 8] = ps[mt*2+1];
                ssq [wnIdx * 128 + lr + 8] = pq[mt*2+1];
            }
        }
        __syncthreads();
        #pragma unroll
        for (int mt = 0; mt < 4; mt++) {
            int lr0 = wm + mt * 16 + (lane >> 2);
            int lr1 = lr0 + 8;
            float s0 = ssum[lr0] + ssum[128+lr0] + ssum[256+lr0] + ssum[384+lr0];
            float q0 = ssq[lr0]  + ssq[128+lr0]  + ssq[256+lr0]  + ssq[384+lr0];
            float s1 = ssum[lr1] + ssum[128+lr1] + ssum[256+lr1] + ssum[384+lr1];
            float q1 = ssq[lr1]  + ssq[128+lr1]  + ssq[256+lr1]  + ssq[384+lr1];
            float mu0 = s0 * (1.f/128.f);
            float iv0 = rsqrtf(q0 * (1.f/128.f) - mu0*mu0 + 1e-5f);
            float mu1 = s1 * (1.f/128.f);
            float iv1 = rsqrtf(q1 * (1.f/128.f) - mu1*mu1 + 1e-5f);
            #pragma unroll
            for (int nt = 0; nt < 4; nt++) {
                int gc = wn + nt * 8 + 2 * (lane & 3);
                float g0 = gammap[gc], g1 = gammap[gc+1];
                float b0 = betap[gc],  b1 = betap[gc+1];
                C[xr[mt*2]   + gc]     = (c[mt][nt][0] - mu0) * iv0 * g0 + b0;
                C[xr[mt*2]   + gc + 1] = (c[mt][nt][1] - mu0) * iv0 * g1 + b1;
                C[xr[mt*2+1] + gc]     = (c[mt][nt][2] - mu1) * iv1 * g0 + b0;
                C[xr[mt*2+1] + gc + 1] = (c[mt][nt][3] - mu1) * iv1 * g1 + b1;
            }
        }
        return;
    }

    #pragma unroll
    for (int mt = 0; mt < 4; mt++) {
        #pragma unroll
        for (int nt = 0; nt < 4; nt++) {
            int gr = blockM + wm + mt * 16 + (lane >> 2);
            int gc = blockN + wn + nt * 8 + 2 * (lane & 3);
            float bv0 = bias[gc], bv1 = bias[gc + 1];
            float v00 = c[mt][nt][0] + bv0, v01 = c[mt][nt][1] + bv1;
            float v10 = c[mt][nt][2] + bv0, v11 = c[mt][nt][3] + bv1;
            int gr1 = gr + 8;
            if (MODE == 0) {
                float* p0 = C + (size_t)gr * N + gc;
                float* p1 = C + (size_t)gr1 * N + gc;
                p0[0] = v00; p0[1] = v01; p1[0] = v10; p1[1] = v11;
            } else if (MODE == 1 || MODE == 5) {
                float r00 = rnd_tf32(v00), r01 = rnd_tf32(v01);
                float r10 = rnd_tf32(v10), r11 = rnd_tf32(v11);
                float* p0 = C + (size_t)gr * N + gc;
                float* p1 = C + (size_t)gr1 * N + gc;
                p0[0] = r00; p0[1] = r01; p1[0] = r10; p1[1] = r11;
                if (MODE == 5) {
                    if (gr >= 11 * BN_) {
                        float* e0 = extra + (size_t)(gr - 11 * BN_) * 128 + gc;
                        e0[0] = r00; e0[1] = r01;
                    }
                    if (gr1 >= 11 * BN_) {
                        float* e1 = extra + (size_t)(gr1 - 11 * BN_) * 128 + gc;
                        e1[0] = r10; e1[1] = r11;
                    }
                }
            } else if (MODE == 2) {
                int t0 = gr >> 14, rem0 = gr & 16383;
                size_t or0 = (size_t)((rem0 >> 9) * 12 + t0) * 512 + (rem0 & 511);
                int t1 = gr1 >> 14, rem1 = gr1 & 16383;
                size_t or1 = (size_t)((rem1 >> 9) * 12 + t1) * 512 + (rem1 & 511);
                float* p0 = C + or0 * 256 + gc;
                float* p1 = C + or1 * 256 + gc;
                p0[0] = v00; p0[1] = v01; p1[0] = v10; p1[1] = v11;
            } else if (MODE == 3) {
                float* p0 = C + (size_t)gr * N + gc;
                float* p1 = C + (size_t)gr1 * N + gc;
                p0[0] = v00; p0[1] = v01; p1[0] = v10; p1[1] = v11;
                if (gc >= 128 && gc < 256) {
                    *(__half2*)(Kc + (size_t)gr * 128 + gc - 128)  = __floats2half2_rn(v00, v01);
                    *(__half2*)(Kc + (size_t)gr1 * 128 + gc - 128) = __floats2half2_rn(v10, v11);
                } else if (gc >= 256) {
                    *(__half2*)(Vc + (size_t)gr * 128 + gc - 256)  = __floats2half2_rn(v00, v01);
                    *(__half2*)(Vc + (size_t)gr1 * 128 + gc - 256) = __floats2half2_rn(v10, v11);
                }
            } else { // MODE 4
                if (gc < 128) {
                    float* p0 = C + (size_t)gr * 128 + gc;
                    float* p1 = C + (size_t)gr1 * 128 + gc;
                    p0[0] = v00; p0[1] = v01; p1[0] = v10; p1[1] = v11;
                } else if (gc < 256) {
                    *(__half2*)(Kc + ((size_t)pos * BN_ + gr) * 128 + gc - 128)  = __floats2half2_rn(v00, v01);
                    *(__half2*)(Kc + ((size_t)pos * BN_ + gr1) * 128 + gc - 128) = __floats2half2_rn(v10, v11);
                } else {
                    *(__half2*)(Vc + ((size_t)pos * BN_ + gr) * 128 + gc - 256)  = __floats2half2_rn(v00, v01);
                    *(__half2*)(Vc + ((size_t)pos * BN_ + gr1) * 128 + gc - 256) = __floats2half2_rn(v10, v11);
                }
            }
        }
    }
}

// ---------------- fused GRU step: C = Ah@Whh^T (+bhh), gates vs GI, outputs h / h+pe ----
// Tile: 128 rows x 384 cols in ONE CTA (grid = M/128 = 128 CTAs -> single wave).
// 256 threads, 8 warps as 2x4, warp tile 64x96. 3-stage cp.async.
// smem: staging A 3x2560 + W 3x7680 (30720 fl), overlaid planes r/z (2 x 128x132).
#define GRU_SMEM_FLOATS (2 * 128 * 132)
#define GRU_SMEM_BYTES  (GRU_SMEM_FLOATS * 4)

__global__ __launch_bounds__(256) void gemm_gru(
    const float* __restrict__ Ah,     // h_prev, M x 128 (tf32-rounded)
    const float* __restrict__ Whh,    // 384 x 128 tf32-rounded
    const float* __restrict__ bhh,    // 384
    const float* __restrict__ GI,     // M x 384 (x-part gates, bias included)
    const float* __restrict__ pe_row, // 128
    float* __restrict__ Hnew, float* __restrict__ Hpe)
{
    extern __shared__ float sm[];
    const int tid = threadIdx.x, lane = tid & 31, warp = tid >> 5;
    const int wm = (warp >> 2) * 64;       // 0,64
    const int wn = (warp & 3) * 96;        // 0,96,192,288
    const int blockM = blockIdx.x * 128;

    const int arow = tid >> 1;             // 0..127
    const int koff = (tid & 1) * 8;
    const float* Ag = Ah + (size_t)(blockM + arow) * 128 + koff;
    uint32_t smb = (uint32_t)__cvta_generic_to_shared(sm);
    uint32_t a_s0 = smb + (uint32_t)(arow * 20 + koff) * 4;

    #define GLOADSTAGE(S, KB) do { \
        uint32_t as_ = a_s0 + (S) * 2560u * 4u; const float* ag_ = Ag + (KB); \
        CP16(as_, ag_); CP16(as_ + 16, ag_ + 4); \
        _Pragma("unroll") \
        for (int j = 0; j < 3; j++) { \
            int wrow = arow + j * 128; \
            uint32_t ws_ = smb + (uint32_t)(7680 + (S) * 7680 + wrow * 20 + koff) * 4; \
            const float* wg_ = Whh + (size_t)wrow * 128 + koff + (KB); \
            CP16(ws_, wg_); CP16(ws_ + 16, wg_ + 4); \
        } \
    } while (0)

    float acc[4][12][4];
    #pragma unroll
    for (int i = 0; i < 4; i++)
        #pragma unroll
        for (int j = 0; j < 12; j++)
            #pragma unroll
            for (int r = 0; r < 4; r++) acc[i][j][r] = 0.f;

    GLOADSTAGE(0, 0);
    asm volatile("cp.async.commit_group;");
    GLOADSTAGE(1, 16);
    asm volatile("cp.async.commit_group;");

    #pragma unroll
    for (int it = 0; it < 8; ++it) {
        asm volatile("cp.async.wait_group 1;");
        __syncthreads();
        if (it + 2 < 8) GLOADSTAGE((it + 2) % 3, (it + 2) * 16);
        asm volatile("cp.async.commit_group;");

        const float* Ab = sm + (it % 3) * 2560;
        const float* Wb = sm + 7680 + (it % 3) * 7680;
        #pragma unroll
        for (int ks = 0; ks < 16; ks += 8) {
            const int kc = ks + (lane & 3);
            unsigned af[4][4];
            #pragma unroll
            for (int mt = 0; mt < 4; mt++) {
                int row = wm + mt * 16 + (lane >> 2);
                af[mt][0] = __float_as_uint(Ab[row * 20 + kc]);
                af[mt][1] = __float_as_uint(Ab[(row + 8) * 20 + kc]);
                af[mt][2] = __float_as_uint(Ab[row * 20 + kc + 4]);
                af[mt][3] = __float_as_uint(Ab[(row + 8) * 20 + kc + 4]);
            }
            #pragma unroll
            for (int nt = 0; nt < 12; nt++) {
                int col = wn + nt * 8 + (lane >> 2);
                unsigned b0 = __float_as_uint(Wb[col * 20 + kc]);
                unsigned b1 = __float_as_uint(Wb[col * 20 + kc + 4]);
                unsigned bf_[2] = {b0, b1};
                #pragma unroll
                for (int mt = 0; mt < 4; mt++)
                    mma1688(acc[mt][nt], af[mt], bf_);
            }
        }
    }
    #undef GLOADSTAGE

    asm volatile("cp.async.wait_group 0;");
    __syncthreads();

    float* sr = sm;                 // r plane [128][132]
    float* sz = sm + 128 * 132;     // z plane

    // phase 1: r/z gates -> smem
    #pragma unroll
    for (int mt = 0; mt < 4; mt++) {
        int lr0 = wm + mt * 16 + (lane >> 2);
        int gr0 = blockM + lr0;
        #pragma unroll
        for (int nt = 0; nt < 12; nt++) {
            int gc = wn + nt * 8 + 2 * (lane & 3);
            int gate = gc >> 7;
            if (gate == 2) continue;
            int d = gc & 127;
            float* sp = (gate == 0) ? sr : sz;
            float b0 = bhh[gc], b1 = bhh[gc + 1];
            size_t g0 = (size_t)gr0 * 384 + gc;
            size_t g1 = (size_t)(gr0 + 8) * 384 + gc;
            sp[lr0 * 132 + d]           = sigmoid_f(GI[g0]     + acc[mt][nt][0] + b0);
            sp[lr0 * 132 + d + 1]       = sigmoid_f(GI[g0 + 1] + acc[mt][nt][1] + b1);
            sp[(lr0 + 8) * 132 + d]     = sigmoid_f(GI[g1]     + acc[mt][nt][2] + b0);
            sp[(lr0 + 8) * 132 + d + 1] = sigmoid_f(GI[g1 + 1] + acc[mt][nt][3] + b1);
        }
    }
    __syncthreads();

    // phase 2: n gate + combine + write h, h+pe
    #pragma unroll
    for (int mt = 0; mt < 4; mt++) {
        int lr0 = wm + mt * 16 + (lane >> 2);
        int gr0 = blockM + lr0;
        #pragma unroll
        for (int nt = 0; nt < 12; nt++) {
            int gc = wn + nt * 8 + 2 * (lane & 3);
            if ((gc >> 7) != 2) continue;
            int d = gc & 127;
            float b0 = bhh[gc], b1 = bhh[gc + 1];
            size_t g0 = (size_t)gr0 * 384 + gc;
            size_t g1 = (size_t)(gr0 + 8) * 384 + gc;
            float pe0 = pe_row[d], pe1 = pe_row[d + 1];
            // row gr0
            {
                float r0 = sr[lr0 * 132 + d],     r1 = sr[lr0 * 132 + d + 1];
                float z0 = sz[lr0 * 132 + d],     z1 = sz[lr0 * 132 + d + 1];
                float n0 = tanh_f(GI[g0]     + r0 * (acc[mt][nt][0] + b0));
                float n1 = tanh_f(GI[g0 + 1] + r1 * (acc[mt][nt][1] + b1));
                float h0 = Ah[(size_t)gr0 * 128 + d], h1 = Ah[(size_t)gr0 * 128 + d + 1];
                float o0 = (1.f - z0) * n0 + z0 * h0;
                float o1 = (1.f - z1) * n1 + z1 * h1;
                Hnew[(size_t)gr0 * 128 + d]     = rnd_tf32(o0);
                Hnew[(size_t)gr0 * 128 + d + 1] = rnd_tf32(o1);
                Hpe [(size_t)gr0 * 128 + d]     = rnd_tf32(o0 + pe0);
                Hpe [(size_t)gr0 * 128 + d + 1] = rnd_tf32(o1 + pe1);
            }
            // row gr0+8
            {
                int lr1 = lr0 + 8, gr1 = gr0 + 8;
                float r0 = sr[lr1 * 132 + d],     r1 = sr[lr1 * 132 + d + 1];
                float z0 = sz[lr1 * 132 + d],     z1 = sz[lr1 * 132 + d + 1];
                float n0 = tanh_f(GI[g1]     + r0 * (acc[mt][nt][2] + b0));
                float n1 = tanh_f(GI[g1 + 1] + r1 * (acc[mt][nt][3] + b1));
                float h0 = Ah[(size_t)gr1 * 128 + d], h1 = Ah[(size_t)gr1 * 128 + d + 1];
                float o0 = (1.f - z0) * n0 + z0 * h0;
                float o1 = (1.f - z1) * n1 + z1 * h1;
                Hnew[(size_t)gr1 * 128 + d]     = rnd_tf32(o0);
                Hnew[(size_t)gr1 * 128 + d + 1] = rnd_tf32(o1);
                Hpe [(size_t)gr1 * 128 + d]     = rnd_tf32(o0 + pe0);
                Hpe [(size_t)gr1 * 128 + d + 1] = rnd_tf32(o1 + pe1);
            }
        }
    }
}

// ---------------- weight prep ----------------
__global__ void roundw_a_kernel(const float* __restrict__ w_ih, const float* __restrict__ w_hh,
                                const float* __restrict__ in_w,
                                float* wih_r, float* whh_r, float* inw_r) {
    int i = blockIdx.x * blockDim.x + threadIdx.x;
    if (i < 49152)       wih_r[i]         = rnd_tf32(w_ih[i]);
    else if (i < 98304)  whh_r[i - 49152] = rnd_tf32(w_hh[i - 49152]);
    else if (i < 147456) inw_r[i - 98304] = rnd_tf32(in_w[i - 98304]);
}
__global__ void roundw_b_kernel(const float* __restrict__ out_w, const float* __restrict__ back_w,
                                const float* __restrict__ fore_w,
                                float* outw_r, float* backw_r, float* forew_r) {
    int i = blockIdx.x * blockDim.x + threadIdx.x;
    if (i < 16384)      outw_r[i]          = rnd_tf32(out_w[i]);
    else if (i < 32768) backw_r[i - 16384] = rnd_tf32(back_w[i - 16384]);
    else if (i < 65536) forew_r[i - 32768] = rnd_tf32(fore_w[i - 32768]);
}

__global__ void pe_init_kernel(float* pe) {
    int idx = blockIdx.x * blockDim.x + threadIdx.x;
    if (idx >= 64 * 128) return;
    int pos = idx >> 7, d = idx & 127;
    int j = d >> 1;
    float div = expf((float)(2 * j) * (-logf(10000.f) / 128.f));
    float ang = (float)pos * div;
    pe[idx] = (d & 1) ? cosf(ang) : sinf(ang);
}

// Wf = w_ih @ attn_out_w (384x128), bf = w_ih @ b_out + b_ih
__global__ void wf_build_kernel(const float* __restrict__ w_ih, const float* __restrict__ out_w,
                                const float* __restrict__ b_out, const float* __restrict__ b_ih,
                                float* __restrict__ Wf, float* __restrict__ bf) {
    int idx = blockIdx.x * blockDim.x + threadIdx.x;
    if (idx >= 384 * 128) return;
    int r = idx >> 7, k = idx & 127;
    float acc = 0.f;
    #pragma unroll 4
    for (int j = 0; j < 128; j++) acc += w_ih[r * 128 + j] * out_w[j * 128 + k];
    Wf[idx] = rnd_tf32(acc);
    if (k == 0) {
        float b = 0.f;
        for (int j = 0; j < 128; j++) b += w_ih[r * 128 + j] * b_out[j];
        bf[r] = b + b_ih[r];
    }
}

__global__ void kvpe_kernel(const float* __restrict__ attn_in_w, const float* __restrict__ pe,
                            float* __restrict__ Kpe, float* __restrict__ Vpe) {
    int idx = blockIdx.x * blockDim.x + threadIdx.x;
    if (idx >= 24 * 256) return;
    int pos = idx >> 8, c = idx & 255;
    const float* wrow = attn_in_w + (size_t)(128 + c) * 128;
    const float* prow = pe + pos * 128;
    float acc = 0.f;
    #pragma unroll 4
    for (int d = 0; d < 128; d++) acc += wrow[d] * prow[d];
    if (c < 128) Kpe[pos * 128 + c] = acc;
    else         Vpe[pos * 128 + (c - 128)] = acc;
}

// ---------------- GRU gates (step 0 only: gh = bhh broadcast, h = 0) ----------------
__global__ void gru_gates0_kernel(const float* __restrict__ gi, const float* __restrict__ bhh,
                                  float* __restrict__ hnew, float* __restrict__ hnext,
                                  const float* __restrict__ pe_row, int total) {
    int idx = blockIdx.x * blockDim.x + threadIdx.x;
    if (idx >= total) return;
    int row = idx >> 7, d = idx & 127;
    size_t b3 = (size_t)row * 384;
    float ir = gi[b3 + d], iz = gi[b3 + 128 + d], in_ = gi[b3 + 256 + d];
    float r = sigmoid_f(ir + bhh[d]);
    float z = sigmoid_f(iz + bhh[128 + d]);
    float n = tanh_f(in_ + r * bhh[256 + d]);
    float out = (1.f - z) * n;
    hnew[idx] = rnd_tf32(out);
    hnext[idx] = rnd_tf32(out + pe_row[d]);
}

// ---------------- encoder self-attention (warp per (bn,head)) ----------------
__global__ void enc_attn_kernel(const float* __restrict__ QKV, float* __restrict__ O) {
    int bn = blockIdx.x;
    int w = threadIdx.x >> 5, lane = threadIdx.x & 31;
    __shared__ float q[4][12][32];
    __shared__ float k[4][12][33];
    __shared__ float v[4][12][33];
    __shared__ float s[4][12][13];

    for (int e = lane; e < 12 * 32; e += 32) {
        int l = e >> 5, d = e & 31;
        size_t base = ((size_t)l * BN_ + bn) * 384 + w * 32 + d;
        q[w][l][d] = QKV[base];
        k[w][l][d] = QKV[base + 128];
        v[w][l][d] = QKV[base + 256];
    }
    __syncwarp();
    const float scale = 0.17677669529663687f;
    if (lane < 12) {
        int j = lane;
        #pragma unroll
        for (int i = 0; i < 12; i++) {
            float acc = 0.f;
            #pragma unroll
            for (int d = 0; d < 32; d++) acc += q[w][i][d] * k[w][j][d];
            s[w][i][j] = acc * scale;
        }
    }
    __syncwarp();
    if (lane < 12) {
        int i = lane;
        float mx = -1e30f;
        #pragma unroll
        for (int j = 0; j < 12; j++) mx = fmaxf(mx, s[w][i][j]);
        float sum = 0.f;
        #pragma unroll
        for (int j = 0; j < 12; j++) { float e = __expf(s[w][i][j] - mx); s[w][i][j] = e; sum += e; }
        float inv = __fdividef(1.f, sum);
        #pragma unroll
        for (int j = 0; j < 12; j++) s[w][i][j] *= inv;
    }
    __syncwarp();
    {
        int d = lane;
        #pragma unroll
        for (int i = 0; i < 12; i++) {
            float acc = 0.f;
            #pragma unroll
            for (int j = 0; j < 12; j++) acc += s[w][i][j] * v[w][j][d];
            O[((size_t)i * BN_ + bn) * 128 + w * 32 + d] = rnd_tf32(acc);
        }
    }
}

// ---------------- decode attention (fp16 KV, PE-drift multipliers) ----------------
__global__ void dec_attn_kernel(const float* __restrict__ Qbuf,
                                const __half* __restrict__ Kc, const __half* __restrict__ Vc,
                                const float* __restrict__ Kpe, const float* __restrict__ Vpe,
                                float* __restrict__ O, int t) {
    int len = 12 + t;
    int bn = blockIdx.x;
    int w = threadIdx.x >> 5, lane = threadIdx.x & 31;
    __shared__ float qs[4][32];
    __shared__ float Kb[4][23][33];
    __shared__ float Vb[4][23][33];
    __shared__ float aw[4][23];

    qs[w][lane] = Qbuf[(size_t)bn * 128 + w * 32 + lane];
    for (int e = lane; e < len * 32; e += 32) {
        int i = e >> 5, d = e & 31;
        size_t src = ((size_t)i * BN_ + bn) * 128 + w * 32 + d;
        Kb[w][i][d] = __half2float(Kc[src]);
        Vb[w][i][d] = __half2float(Vc[src]);
    }
    __syncwarp();

    float sc = -1e30f;
    int i = lane;
    if (i < len) {
        float m = (i < 12) ? (float)(t - 1) : (float)(t - i + 12);
        float a = 0.f, ap = 0.f;
        #pragma unroll
        for (int d = 0; d < 32; d++) {
            float qd = qs[w][d];
            a  += Kb[w][i][d] * qd;
            ap += Kpe[i * 128 + w * 32 + d] * qd;
        }
        sc = (a + m * ap) * 0.17677669529663687f;
    }
    float mx = sc;
    #pragma unroll
    for (int o = 16; o > 0; o >>= 1) mx = fmaxf(mx, __shfl_xor_sync(0xffffffffu, mx, o));
    float e = (i < len) ? __expf(sc - mx) : 0.f;
    float sum = e;
    #pragma unroll
    for (int o = 16; o > 0; o >>= 1) sum += __shfl_xor_sync(0xffffffffu, sum, o);
    float a = __fdividef(e, sum);
    if (i < len) aw[w][i] = a;
    __syncwarp();

    int d = lane;
    float acc = 0.f;
    for (int j = 0; j < len; j++) {
        float mj = (j < 12) ? (float)(t - 1) : (float)(t - j + 12);
        acc += aw[w][j] * (Vb[w][j][d] + mj * Vpe[j * 128 + w * 32 + d]);
    }
    O[(size_t)bn * 128 + w * 32 + d] = rnd_tf32(acc);
}

// ---------------- host orchestration ----------------
static inline float* symaddr(const void* sym) {
    void* p = nullptr;
    cudaGetSymbolAddress(&p, sym);
    return (float*)p;
}
static inline __half* symaddr_h(const void* sym) {
    void* p = nullptr;
    cudaGetSymbolAddress(&p, sym);
    return (__half*)p;
}

template <int MODE, int APERM>
static inline void launch_gemm(const float* A, const float* W, const float* b, float* C,
                               int M, int N, int pos = 0,
                               __half* Kc = nullptr, __half* Vc = nullptr,
                               float* extra = nullptr, const float* Xg = nullptr,
                               const float* gam = nullptr, const float* bet = nullptr) {
    gemm3<MODE, APERM><<<dim3(N / 128, M / 128, 1), 256, GSMEM_BYTES>>>(
        A, W, b, C, M, N, pos, Kc, Vc, extra, Xg, gam, bet);
}

extern "C" void kernel_launch(void* const* d_in, const int* in_sizes, int n_in,
                              void* d_out, int out_size) {
    const float* X          = (const float*)d_in[0];
    const float* gru_w_ih   = (const float*)d_in[1];
    const float* gru_w_hh   = (const float*)d_in[2];
    const float* gru_b_ih   = (const float*)d_in[3];
    const float* gru_b_hh   = (const float*)d_in[4];
    const float* attn_in_w  = (const float*)d_in[5];
    const float* attn_in_b  = (const float*)d_in[6];
    const float* attn_out_w = (const float*)d_in[7];
    const float* attn_out_b = (const float*)d_in[8];
    const float* backcast_w = (const float*)d_in[9];
    const float* backcast_b = (const float*)d_in[10];
    const float* forecast_w = (const float*)d_in[11];
    const float* forecast_b = (const float*)d_in[12];
    const float* ln_gamma   = (const float*)d_in[13];
    const float* ln_beta    = (const float*)d_in[14];

    float* out  = (float*)d_out;
    float* res  = out;
    float* fore = out + RES_ELEMS;

    float*  GI    = symaddr(g_GI);
    float*  rnn   = symaddr(g_rnn);
    float*  rnnpe = symaddr(g_rnnpe);
    float*  QKV   = symaddr(g_QKV);
    float*  attn  = symaddr(g_attn);
    float*  Z0    = symaddr(g_Z0);
    __half* Kc    = symaddr_h(g_Kc);
    __half* Vc    = symaddr_h(g_Vc);
    float*  pred  = symaddr(g_pred);
    float*  aresT = symaddr(g_aresT);
    float*  Qbuf  = symaddr(g_Qbuf);
    float*  GIdec = symaddr(g_GIdec);
    float*  gbuf  = symaddr(g_g);
    float*  hlast = symaddr(g_hlast);
    float*  pe    = symaddr(g_pe);
    float*  Kpe   = symaddr(g_Kpe);
    float*  Vpe   = symaddr(g_Vpe);
    float*  wih_r   = symaddr(g_wih_r);
    float*  whh_r   = symaddr(g_whh_r);
    float*  inw_r   = symaddr(g_inw_r);
    float*  outw_r  = symaddr(g_outw_r);
    float*  backw_r = symaddr(g_backw_r);
    float*  forew_r = symaddr(g_forew_r);
    float*  Wf      = symaddr(g_Wf);
    float*  bf      = symaddr(g_bf);

    cudaFuncSetAttribute(gemm3<0,0>, cudaFuncAttributeMaxDynamicSharedMemorySize, GSMEM_BYTES);
    cudaFuncSetAttribute(gemm3<0,1>, cudaFuncAttributeMaxDynamicSharedMemorySize, GSMEM_BYTES);
    cudaFuncSetAttribute(gemm3<1,0>, cudaFuncAttributeMaxDynamicSharedMemorySize, GSMEM_BYTES);
    cudaFuncSetAttribute(gemm3<2,0>, cudaFuncAttributeMaxDynamicSharedMemorySize, GSMEM_BYTES);
    cudaFuncSetAttribute(gemm3<3,0>, cudaFuncAttributeMaxDynamicSharedMemorySize, GSMEM_BYTES);
    cudaFuncSetAttribute(gemm3<4,0>, cudaFuncAttributeMaxDynamicSharedMemorySize, GSMEM_BYTES);
    cudaFuncSetAttribute(gemm3<5,0>, cudaFuncAttributeMaxDynamicSharedMemorySize, GSMEM_BYTES);
    cudaFuncSetAttribute(gemm3<6,0>, cudaFuncAttributeMaxDynamicSharedMemorySize, GSMEM_BYTES);
    cudaFuncSetAttribute(gemm_gru,   cudaFuncAttributeMaxDynamicSharedMemorySize, GRU_SMEM_BYTES);

    const int TPB = 256;

    // ---- prep (big GI GEMM is the 4th launch -> profiled by ncu -s) ----
    roundw_a_kernel<<<(147456 + TPB - 1) / TPB, TPB>>>(gru_w_ih, gru_w_hh, attn_in_w,
                                                       wih_r, whh_r, inw_r);
    roundw_b_kernel<<<(65536 + TPB - 1) / TPB, TPB>>>(attn_out_w, backcast_w, forecast_w,
                                                      outw_r, backw_r, forew_r);
    pe_init_kernel<<<(64 * 128 + TPB - 1) / TPB, TPB>>>(pe);

    // ---- GI for all encoder steps (A read straight from X via row remap) ----
    launch_gemm<0, 1>(X, wih_r, gru_b_ih, GI, LBN_, 384);

    wf_build_kernel<<<(49152 + TPB - 1) / TPB, TPB>>>(gru_w_ih, attn_out_w, attn_out_b,
                                                      gru_b_ih, Wf, bf);
    kvpe_kernel<<<(24 * 256 + TPB - 1) / TPB, TPB>>>(attn_in_w, pe, Kpe, Vpe);

    // ---- GRU encode: step 0 gates-only, then 11x fused gemm_gru ----
    gru_gates0_kernel<<<BN_ * 128 / TPB, TPB>>>(GI, gru_b_hh, rnn, rnnpe, pe, BN_ * 128);
    for (int l = 1; l < 12; l++) {
        gemm_gru<<<128, 256, GRU_SMEM_BYTES>>>(
            rnn + (size_t)(l - 1) * BN_ * 128, whh_r, gru_b_hh,
            GI + (size_t)l * BN_ * 384, pe + l * 128,
            rnn + (size_t)l * BN_ * 128, rnnpe + (size_t)l * BN_ * 128);
    }

    // ---- encoder MHA (QKV gemm scatters fp16 K/V into caches) ----
    launch_gemm<3, 0>(rnnpe, inw_r, attn_in_b, QKV, LBN_, 384, 0, Kc, Vc);
    enc_attn_kernel<<<BN_, 128>>>(QKV, attn);
    launch_gemm<5, 0>(attn, outw_r, attn_out_b, Z0, LBN_, 128, 0, nullptr, nullptr, pred);

    // ---- backcast + residual LN fused into one GEMM ----
    launch_gemm<6, 0>(Z0, backw_r, backcast_b, res, LBN_, 128, 0, nullptr, nullptr,
                      nullptr, X, ln_gamma, ln_beta);

    // ---- decode loop: GIdec gemm -> fused gemm_gru -> proj gemm -> dec_attn ----
    const float* hl = rnn + (size_t)11 * BN_ * 128;
    for (int t = 1; t <= 11; t++) {
        const float* prevA = (t == 1) ? attn + (size_t)11 * BN_ * 128
                                      : aresT + (size_t)(t - 2) * BN_ * 128;
        launch_gemm<0, 0>(prevA, Wf, bf, GIdec, BN_, 384);
        gemm_gru<<<128, 256, GRU_SMEM_BYTES>>>(
            hl, whh_r, gru_b_hh, GIdec, pe + (11 + t) * 128, gbuf, hlast);
        hl = hlast;
        launch_gemm<4, 0>(gbuf, inw_r, attn_in_b, Qbuf, BN_, 384, 11 + t, Kc, Vc);
        dec_attn_kernel<<<BN_, 128>>>(Qbuf, Kc, Vc, Kpe, Vpe,
                                      aresT + (size_t)(t - 1) * BN_ * 128, t);
    }

    // ---- batched output projection for pred[1..11] ----
    launch_gemm<1, 0>(aresT, outw_r, attn_out_b, pred + (size_t)BN_ * 128, 11 * BN_, 128);

    // ---- forecast ----
    launch_gemm<2, 0>(pred, forew_r, forecast_b, fore, LBN_, 256);
}

// round 6
// speedup vs baseline: 1.2473x; 1.2473x over previous
#include <cuda_runtime.h>
#include <cuda_fp16.h>
#include <math.h>
#include <stdint.h>

// ---------------- problem constants ----------------
#define B_    32
#define L_    12
#define N_    512
#define D_    128
#define BN_   16384      // B_*N_
#define LBN_  196608     // L_*BN_
#define FK_   256
#define T_    12
#define RES_ELEMS  25165824ULL   // 32*12*512*128
#define FORE_ELEMS 50331648ULL

// ---------------- device scratch (static, no allocations) ----------------
__device__ float  g_GI    [(size_t)LBN_ * 384];
__device__ float  g_GH    [(size_t)BN_  * 384];
__device__ float  g_rnn   [(size_t)LBN_ * 128];
__device__ float  g_rnnpe [(size_t)LBN_ * 128];
__device__ float  g_QKV   [(size_t)LBN_ * 384];
__device__ float  g_attn  [(size_t)LBN_ * 128];
__device__ float  g_Z0    [(size_t)LBN_ * 128];
__device__ __half g_Kc    [(size_t)23 * BN_ * 128];
__device__ __half g_Vc    [(size_t)23 * BN_ * 128];
__device__ float  g_pred  [(size_t)T_ * BN_ * 128];
__device__ float  g_aresT [(size_t)11 * BN_ * 128];
__device__ float  g_Qbuf  [(size_t)BN_ * 128];
__device__ float  g_GIdec [(size_t)BN_ * 384];
__device__ float  g_GHdec [(size_t)BN_ * 384];
__device__ float  g_g     [(size_t)BN_ * 128];
__device__ float  g_hlast [(size_t)BN_ * 128];
__device__ float  g_pe    [64 * 128];
__device__ float  g_Kpe   [24 * 128];
__device__ float  g_Vpe   [24 * 128];
// pre-rounded (tf32) weights
__device__ float g_wih_r  [49152];
__device__ float g_whh_r  [49152];
__device__ float g_inw_r  [49152];
__device__ float g_outw_r [16384];
__device__ float g_backw_r[16384];
__device__ float g_forew_r[32768];
__device__ float g_Wf     [49152];
__device__ float g_bf     [384];

// ---------------- helpers ----------------
__device__ __forceinline__ float rnd_tf32(float x) {
    unsigned u;
    asm("cvt.rna.tf32.f32 %0, %1;" : "=r"(u) : "f"(x));
    return __uint_as_float(u);
}
__device__ __forceinline__ void mma1688(float c[4], const unsigned a[4], const unsigned b[2]) {
    asm volatile(
        "mma.sync.aligned.m16n8k8.row.col.f32.tf32.tf32.f32 "
        "{%0,%1,%2,%3}, {%4,%5,%6,%7}, {%8,%9}, {%0,%1,%2,%3};\n"
        : "+f"(c[0]), "+f"(c[1]), "+f"(c[2]), "+f"(c[3])
        : "r"(a[0]), "r"(a[1]), "r"(a[2]), "r"(a[3]), "r"(b[0]), "r"(b[1]));
}
__device__ __forceinline__ float sigmoid_f(float x) {
    return __fdividef(1.f, 1.f + __expf(-x));
}
__device__ __forceinline__ float tanh_f(float x) {
    float ex = __expf(2.f * x);
    return 1.f - __fdividef(2.f, ex + 1.f);
}

#define CP16(dst, src) asm volatile("cp.async.cg.shared.global [%0], [%1], 16;" :: "r"(dst), "l"(src))

// ---------------- templated tf32 GEMM: cp.async 3-stage ----------------
// C[M,N] = A[M,128] @ W[N,128]^T + bias ; W pre-rounded tf32.
// MODE 0: plain. 1: plain + tf32-rounded out. 2: forecast permute (N=256).
// 3: QKV full write + scatter cols[128,384) -> fp16 Kc/Vc at row index (N=384).
// 4: proj: cols[0,128)->C stride128, cols[128,384) -> fp16 Kc/Vc at pos (N=384).
// 5: like 1 (N=128) + rows>=11*BN also copied to extra (pred[0]).
// 6: backcast+LN fused (N=128).
// APERM 1: A row remap (l*BN+b*512+n) -> X row (b*12+l)*512+n.
// blockIdx.z selects pointer set (fused pair launches).
#define GSMEM_WORDS (2 * 3 * 2560)
#define GSMEM_BYTES (GSMEM_WORDS * 4)

template <int MODE, int APERM>
__global__ __launch_bounds__(256, 2) void gemm3(
    const float* __restrict__ A0, const float* __restrict__ W0,
    const float* __restrict__ bias0, float* __restrict__ C0,
    const float* __restrict__ A1, const float* __restrict__ W1,
    const float* __restrict__ bias1, float* __restrict__ C1,
    int M, int N, int pos,
    __half* __restrict__ Kc, __half* __restrict__ Vc,
    float* __restrict__ extra,
    const float* __restrict__ Xg, const float* __restrict__ gammap,
    const float* __restrict__ betap)
{
    extern __shared__ float sm[];
    const float* A    = blockIdx.z ? A1    : A0;
    const float* W    = blockIdx.z ? W1    : W0;
    const float* bias = blockIdx.z ? bias1 : bias0;
    float*       C    = blockIdx.z ? C1    : C0;

    const int tid = threadIdx.x, lane = tid & 31, warp = tid >> 5;
    const int wm = (warp >> 2) * 64;
    const int wn = (warp & 3) * 32;
    const int blockM = blockIdx.y * 128;
    const int blockN = blockIdx.x * 128;

    const int arow = tid >> 1;
    const int koff = (tid & 1) * 8;
    const float* Ag;
    if (APERM) {
        int grow = blockM + arow;
        int l = grow >> 14, rem = grow & 16383, b = rem >> 9, n = rem & 511;
        Ag = A + (((size_t)(b * 12 + l) * 512 + n) << 7) + koff;
    } else {
        Ag = A + (size_t)(blockM + arow) * 128 + koff;
    }
    const float* Wg = W + (size_t)(blockN + arow) * 128 + koff;
    uint32_t smb = (uint32_t)__cvta_generic_to_shared(sm);
    uint32_t a_s0 = smb + (uint32_t)(arow * 20 + koff) * 4;
    uint32_t w_s0 = smb + (uint32_t)(7680 + arow * 20 + koff) * 4;

    #define LOADSTAGE(S, KB) do { \
        uint32_t as_ = a_s0 + (S) * 2560u * 4u; const float* ag_ = Ag + (KB); \
        CP16(as_, ag_); CP16(as_ + 16, ag_ + 4); \
        uint32_t ws_ = w_s0 + (S) * 2560u * 4u; const float* wg_ = Wg + (KB); \
        CP16(ws_, wg_); CP16(ws_ + 16, wg_ + 4); \
    } while (0)

    float c[4][4][4];
    #pragma unroll
    for (int i = 0; i < 4; i++)
        #pragma unroll
        for (int j = 0; j < 4; j++)
            #pragma unroll
            for (int r = 0; r < 4; r++) c[i][j][r] = 0.f;

    LOADSTAGE(0, 0);
    asm volatile("cp.async.commit_group;");
    LOADSTAGE(1, 16);
    asm volatile("cp.async.commit_group;");

    #pragma unroll
    for (int it = 0; it < 8; ++it) {
        asm volatile("cp.async.wait_group 1;");
        __syncthreads();
        if (it + 2 < 8) LOADSTAGE((it + 2) % 3, (it + 2) * 16);
        asm volatile("cp.async.commit_group;");

        const float* Ab = sm + (it % 3) * 2560;
        const float* Wb = sm + 7680 + (it % 3) * 2560;
        #pragma unroll
        for (int ks = 0; ks < 16; ks += 8) {
            unsigned af[4][4], bf_[4][2];
            const int kc = ks + (lane & 3);
            #pragma unroll
            for (int mt = 0; mt < 4; mt++) {
                int row = wm + mt * 16 + (lane >> 2);
                af[mt][0] = __float_as_uint(Ab[row * 20 + kc]);
                af[mt][1] = __float_as_uint(Ab[(row + 8) * 20 + kc]);
                af[mt][2] = __float_as_uint(Ab[row * 20 + kc + 4]);
                af[mt][3] = __float_as_uint(Ab[(row + 8) * 20 + kc + 4]);
            }
            #pragma unroll
            for (int nt = 0; nt < 4; nt++) {
                int col = wn + nt * 8 + (lane >> 2);
                bf_[nt][0] = __float_as_uint(Wb[col * 20 + kc]);
                bf_[nt][1] = __float_as_uint(Wb[col * 20 + kc + 4]);
            }
            #pragma unroll
            for (int mt = 0; mt < 4; mt++)
                #pragma unroll
                for (int nt = 0; nt < 4; nt++)
                    mma1688(c[mt][nt], af[mt], bf_[nt]);
        }
    }
    #undef LOADSTAGE

    // ================= epilogues =================
    if (MODE == 6) {
        asm volatile("cp.async.wait_group 0;");
        __syncthreads();
        float* ssum = sm;
        float* ssq  = sm + 512;
        float ps[8], pq[8];
        #pragma unroll
        for (int p = 0; p < 8; p++) { ps[p] = 0.f; pq[p] = 0.f; }
        size_t xr[8];
        #pragma unroll
        for (int mt = 0; mt < 4; mt++) {
            int gr0 = blockM + wm + mt * 16 + (lane >> 2);
            int gr1 = gr0 + 8;
            int l0 = gr0 >> 14, r0 = gr0 & 16383;
            xr[mt * 2]     = (((size_t)((r0 >> 9) * 12 + l0) * 512 + (r0 & 511)) << 7);
            int l1 = gr1 >> 14, r1 = gr1 & 16383;
            xr[mt * 2 + 1] = (((size_t)((r1 >> 9) * 12 + l1) * 512 + (r1 & 511)) << 7);
            #pragma unroll
            for (int nt = 0; nt < 4; nt++) {
                int gc = wn + nt * 8 + 2 * (lane & 3);
                float bv0 = bias[gc], bv1 = bias[gc + 1];
                float u00 = Xg[xr[mt*2]   + gc]     - fmaxf(c[mt][nt][0] + bv0, 0.f);
                float u01 = Xg[xr[mt*2]   + gc + 1] - fmaxf(c[mt][nt][1] + bv1, 0.f);
                float u10 = Xg[xr[mt*2+1] + gc]     - fmaxf(c[mt][nt][2] + bv0, 0.f);
                float u11 = Xg[xr[mt*2+1] + gc + 1] - fmaxf(c[mt][nt][3] + bv1, 0.f);
                c[mt][nt][0] = u00; c[mt][nt][1] = u01;
                c[mt][nt][2] = u10; c[mt][nt][3] = u11;
                ps[mt*2]   += u00 + u01;  pq[mt*2]   += u00*u00 + u01*u01;
                ps[mt*2+1] += u10 + u11;  pq[mt*2+1] += u10*u10 + u11*u11;
            }
        }
        #pragma unroll
        for (int o = 1; o < 4; o <<= 1) {
            #pragma unroll
            for (int p = 0; p < 8; p++) {
                ps[p] += __shfl_xor_sync(0xffffffffu, ps[p], o);
                pq[p] += __shfl_xor_sync(0xffffffffu, pq[p], o);
            }
        }
        int wnIdx = warp & 3;
        if ((lane & 3) == 0) {
            #pragma unroll
            for (int mt = 0; mt < 4; mt++) {
                int lr = wm + mt * 16 + (lane >> 2);
                ssum[wnIdx * 128 + lr]     = ps[mt*2];
                ssq [wnIdx * 128 + lr]     = pq[mt*2];
                ssum[wnIdx * 128 + lr + 8] = ps[mt*2+1];
                ssq [wnIdx * 128 + lr + 8] = pq[mt*2+1];
            }
        }
        __syncthreads();
        #pragma unroll
        for (int mt = 0; mt < 4; mt++) {
            int lr0 = wm + mt * 16 + (lane >> 2);
            int lr1 = lr0 + 8;
            float s0 = ssum[lr0] + ssum[128+lr0] + ssum[256+lr0] + ssum[384+lr0];
            float q0 = ssq[lr0]  + ssq[128+lr0]  + ssq[256+lr0]  + ssq[384+lr0];
            float s1 = ssum[lr1] + ssum[128+lr1] + ssum[256+lr1] + ssum[384+lr1];
            float q1 = ssq[lr1]  + ssq[128+lr1]  + ssq[256+lr1]  + ssq[384+lr1];
            float mu0 = s0 * (1.f/128.f);
            float iv0 = rsqrtf(q0 * (1.f/128.f) - mu0*mu0 + 1e-5f);
            float mu1 = s1 * (1.f/128.f);
            float iv1 = rsqrtf(q1 * (1.f/128.f) - mu1*mu1 + 1e-5f);
            #pragma unroll
            for (int nt = 0; nt < 4; nt++) {
                int gc = wn + nt * 8 + 2 * (lane & 3);
                float g0 = gammap[gc], g1 = gammap[gc+1];
                float b0 = betap[gc],  b1 = betap[gc+1];
                C[xr[mt*2]   + gc]     = (c[mt][nt][0] - mu0) * iv0 * g0 + b0;
                C[xr[mt*2]   + gc + 1] = (c[mt][nt][1] - mu0) * iv0 * g1 + b1;
                C[xr[mt*2+1] + gc]     = (c[mt][nt][2] - mu1) * iv1 * g0 + b0;
                C[xr[mt*2+1] + gc + 1] = (c[mt][nt][3] - mu1) * iv1 * g1 + b1;
            }
        }
        return;
    }

    #pragma unroll
    for (int mt = 0; mt < 4; mt++) {
        #pragma unroll
        for (int nt = 0; nt < 4; nt++) {
            int gr = blockM + wm + mt * 16 + (lane >> 2);
            int gc = blockN + wn + nt * 8 + 2 * (lane & 3);
            float bv0 = bias[gc], bv1 = bias[gc + 1];
            float v00 = c[mt][nt][0] + bv0, v01 = c[mt][nt][1] + bv1;
            float v10 = c[mt][nt][2] + bv0, v11 = c[mt][nt][3] + bv1;
            int gr1 = gr + 8;
            if (MODE == 0) {
                float* p0 = C + (size_t)gr * N + gc;
                float* p1 = C + (size_t)gr1 * N + gc;
                p0[0] = v00; p0[1] = v01; p1[0] = v10; p1[1] = v11;
            } else if (MODE == 1 || MODE == 5) {
                float r00 = rnd_tf32(v00), r01 = rnd_tf32(v01);
                float r10 = rnd_tf32(v10), r11 = rnd_tf32(v11);
                float* p0 = C + (size_t)gr * N + gc;
                float* p1 = C + (size_t)gr1 * N + gc;
                p0[0] = r00; p0[1] = r01; p1[0] = r10; p1[1] = r11;
                if (MODE == 5) {
                    if (gr >= 11 * BN_) {
                        float* e0 = extra + (size_t)(gr - 11 * BN_) * 128 + gc;
                        e0[0] = r00; e0[1] = r01;
                    }
                    if (gr1 >= 11 * BN_) {
                        float* e1 = extra + (size_t)(gr1 - 11 * BN_) * 128 + gc;
                        e1[0] = r10; e1[1] = r11;
                    }
                }
            } else if (MODE == 2) {
                int t0 = gr >> 14, rem0 = gr & 16383;
                size_t or0 = (size_t)((rem0 >> 9) * 12 + t0) * 512 + (rem0 & 511);
                int t1 = gr1 >> 14, rem1 = gr1 & 16383;
                size_t or1 = (size_t)((rem1 >> 9) * 12 + t1) * 512 + (rem1 & 511);
                float* p0 = C + or0 * 256 + gc;
                float* p1 = C + or1 * 256 + gc;
                p0[0] = v00; p0[1] = v01; p1[0] = v10; p1[1] = v11;
            } else if (MODE == 3) {
                float* p0 = C + (size_t)gr * N + gc;
                float* p1 = C + (size_t)gr1 * N + gc;
                p0[0] = v00; p0[1] = v01; p1[0] = v10; p1[1] = v11;
                if (gc >= 128 && gc < 256) {
                    *(__half2*)(Kc + (size_t)gr * 128 + gc - 128)  = __floats2half2_rn(v00, v01);
                    *(__half2*)(Kc + (size_t)gr1 * 128 + gc - 128) = __floats2half2_rn(v10, v11);
                } else if (gc >= 256) {
                    *(__half2*)(Vc + (size_t)gr * 128 + gc - 256)  = __floats2half2_rn(v00, v01);
                    *(__half2*)(Vc + (size_t)gr1 * 128 + gc - 256) = __floats2half2_rn(v10, v11);
                }
            } else { // MODE 4
                if (gc < 128) {
                    float* p0 = C + (size_t)gr * 128 + gc;
                    float* p1 = C + (size_t)gr1 * 128 + gc;
                    p0[0] = v00; p0[1] = v01; p1[0] = v10; p1[1] = v11;
                } else if (gc < 256) {
                    *(__half2*)(Kc + ((size_t)pos * BN_ + gr) * 128 + gc - 128)  = __floats2half2_rn(v00, v01);
                    *(__half2*)(Kc + ((size_t)pos * BN_ + gr1) * 128 + gc - 128) = __floats2half2_rn(v10, v11);
                } else {
                    *(__half2*)(Vc + ((size_t)pos * BN_ + gr) * 128 + gc - 256)  = __floats2half2_rn(v00, v01);
                    *(__half2*)(Vc + ((size_t)pos * BN_ + gr1) * 128 + gc - 256) = __floats2half2_rn(v10, v11);
                }
            }
        }
    }
}

// ---------------- weight prep ----------------
__global__ void roundw_a_kernel(const float* __restrict__ w_ih, const float* __restrict__ w_hh,
                                const float* __restrict__ in_w,
                                float* wih_r, float* whh_r, float* inw_r) {
    int i = blockIdx.x * blockDim.x + threadIdx.x;
    if (i < 49152)       wih_r[i]         = rnd_tf32(w_ih[i]);
    else if (i < 98304)  whh_r[i - 49152] = rnd_tf32(w_hh[i - 49152]);
    else if (i < 147456) inw_r[i - 98304] = rnd_tf32(in_w[i - 98304]);
}
__global__ void roundw_b_kernel(const float* __restrict__ out_w, const float* __restrict__ back_w,
                                const float* __restrict__ fore_w,
                                float* outw_r, float* backw_r, float* forew_r) {
    int i = blockIdx.x * blockDim.x + threadIdx.x;
    if (i < 16384)      outw_r[i]          = rnd_tf32(out_w[i]);
    else if (i < 32768) backw_r[i - 16384] = rnd_tf32(back_w[i - 16384]);
    else if (i < 65536) forew_r[i - 32768] = rnd_tf32(fore_w[i - 32768]);
}

__global__ void pe_init_kernel(float* pe) {
    int idx = blockIdx.x * blockDim.x + threadIdx.x;
    if (idx >= 64 * 128) return;
    int pos = idx >> 7, d = idx & 127;
    int j = d >> 1;
    float div = expf((float)(2 * j) * (-logf(10000.f) / 128.f));
    float ang = (float)pos * div;
    pe[idx] = (d & 1) ? cosf(ang) : sinf(ang);
}

// Wf = w_ih @ attn_out_w (384x128), bf = w_ih @ b_out + b_ih
__global__ void wf_build_kernel(const float* __restrict__ w_ih, const float* __restrict__ out_w,
                                const float* __restrict__ b_out, const float* __restrict__ b_ih,
                                float* __restrict__ Wf, float* __restrict__ bf) {
    int idx = blockIdx.x * blockDim.x + threadIdx.x;
    if (idx >= 384 * 128) return;
    int r = idx >> 7, k = idx & 127;
    float acc = 0.f;
    #pragma unroll 4
    for (int j = 0; j < 128; j++) acc += w_ih[r * 128 + j] * out_w[j * 128 + k];
    Wf[idx] = rnd_tf32(acc);
    if (k == 0) {
        float b = 0.f;
        for (int j = 0; j < 128; j++) b += w_ih[r * 128 + j] * b_out[j];
        bf[r] = b + b_ih[r];
    }
}

__global__ void kvpe_kernel(const float* __restrict__ attn_in_w, const float* __restrict__ pe,
                            float* __restrict__ Kpe, float* __restrict__ Vpe) {
    int idx = blockIdx.x * blockDim.x + threadIdx.x;
    if (idx >= 24 * 256) return;
    int pos = idx >> 8, c = idx & 255;
    const float* wrow = attn_in_w + (size_t)(128 + c) * 128;
    const float* prow = pe + pos * 128;
    float acc = 0.f;
    #pragma unroll 4
    for (int d = 0; d < 128; d++) acc += wrow[d] * prow[d];
    if (c < 128) Kpe[pos * 128 + c] = acc;
    else         Vpe[pos * 128 + (c - 128)] = acc;
}

// ---------------- GRU gates (fused h / h+pe outputs) ----------------
// gh == nullptr -> use bhh broadcast (first step). h == nullptr -> h = 0.
__global__ void gru_gates_kernel(const float* __restrict__ gi, const float* __restrict__ gh,
                                 const float* __restrict__ h, float* __restrict__ hnew,
                                 float* __restrict__ hnext, const float* __restrict__ pe_row,
                                 const float* __restrict__ bhh, int total) {
    int idx = blockIdx.x * blockDim.x + threadIdx.x;
    if (idx >= total) return;
    int row = idx >> 7, d = idx & 127;
    size_t b3 = (size_t)row * 384;
    float ir = gi[b3 + d], iz = gi[b3 + 128 + d], in_ = gi[b3 + 256 + d];
    float hr, hz, hn;
    if (gh) { hr = gh[b3 + d]; hz = gh[b3 + 128 + d]; hn = gh[b3 + 256 + d]; }
    else    { hr = bhh[d];     hz = bhh[128 + d];     hn = bhh[256 + d]; }
    float hv = h ? h[idx] : 0.f;
    float r = sigmoid_f(ir + hr);
    float z = sigmoid_f(iz + hz);
    float n = tanh_f(in_ + r * hn);
    float out = (1.f - z) * n + z * hv;
    hnew[idx] = rnd_tf32(out);
    if (hnext) hnext[idx] = rnd_tf32(out + pe_row[d]);
}

// ---------------- encoder self-attention (warp per (bn,head)) ----------------
__global__ void enc_attn_kernel(const float* __restrict__ QKV, float* __restrict__ O) {
    int bn = blockIdx.x;
    int w = threadIdx.x >> 5, lane = threadIdx.x & 31;
    __shared__ float q[4][12][32];
    __shared__ float k[4][12][33];
    __shared__ float v[4][12][33];
    __shared__ float s[4][12][13];

    for (int e = lane; e < 12 * 32; e += 32) {
        int l = e >> 5, d = e & 31;
        size_t base = ((size_t)l * BN_ + bn) * 384 + w * 32 + d;
        q[w][l][d] = QKV[base];
        k[w][l][d] = QKV[base + 128];
        v[w][l][d] = QKV[base + 256];
    }
    __syncwarp();
    const float scale = 0.17677669529663687f;
    if (lane < 12) {
        int j = lane;
        #pragma unroll
        for (int i = 0; i < 12; i++) {
            float acc = 0.f;
            #pragma unroll
            for (int d = 0; d < 32; d++) acc += q[w][i][d] * k[w][j][d];
            s[w][i][j] = acc * scale;
        }
    }
    __syncwarp();
    if (lane < 12) {
        int i = lane;
        float mx = -1e30f;
        #pragma unroll
        for (int j = 0; j < 12; j++) mx = fmaxf(mx, s[w][i][j]);
        float sum = 0.f;
        #pragma unroll
        for (int j = 0; j < 12; j++) { float e = __expf(s[w][i][j] - mx); s[w][i][j] = e; sum += e; }
        float inv = __fdividef(1.f, sum);
        #pragma unroll
        for (int j = 0; j < 12; j++) s[w][i][j] *= inv;
    }
    __syncwarp();
    {
        int d = lane;
        #pragma unroll
        for (int i = 0; i < 12; i++) {
            float acc = 0.f;
            #pragma unroll
            for (int j = 0; j < 12; j++) acc += s[w][i][j] * v[w][j][d];
            O[((size_t)i * BN_ + bn) * 128 + w * 32 + d] = rnd_tf32(acc);
        }
    }
}

// ---------------- decode attention (fp16 KV, PE-drift multipliers) ----------------
__global__ void dec_attn_kernel(const float* __restrict__ Qbuf,
                                const __half* __restrict__ Kc, const __half* __restrict__ Vc,
                                const float* __restrict__ Kpe, const float* __restrict__ Vpe,
                                float* __restrict__ O, int t) {
    int len = 12 + t;
    int bn = blockIdx.x;
    int w = threadIdx.x >> 5, lane = threadIdx.x & 31;
    __shared__ float qs[4][32];
    __shared__ float Kb[4][23][33];
    __shared__ float Vb[4][23][33];
    __shared__ float aw[4][23];

    qs[w][lane] = Qbuf[(size_t)bn * 128 + w * 32 + lane];
    for (int e = lane; e < len * 32; e += 32) {
        int i = e >> 5, d = e & 31;
        size_t src = ((size_t)i * BN_ + bn) * 128 + w * 32 + d;
        Kb[w][i][d] = __half2float(Kc[src]);
        Vb[w][i][d] = __half2float(Vc[src]);
    }
    __syncwarp();

    float sc = -1e30f;
    int i = lane;
    if (i < len) {
        float m = (i < 12) ? (float)(t - 1) : (float)(t - i + 12);
        float a = 0.f, ap = 0.f;
        #pragma unroll
        for (int d = 0; d < 32; d++) {
            float qd = qs[w][d];
            a  += Kb[w][i][d] * qd;
            ap += Kpe[i * 128 + w * 32 + d] * qd;
        }
        sc = (a + m * ap) * 0.17677669529663687f;
    }
    float mx = sc;
    #pragma unroll
    for (int o = 16; o > 0; o >>= 1) mx = fmaxf(mx, __shfl_xor_sync(0xffffffffu, mx, o));
    float e = (i < len) ? __expf(sc - mx) : 0.f;
    float sum = e;
    #pragma unroll
    for (int o = 16; o > 0; o >>= 1) sum += __shfl_xor_sync(0xffffffffu, sum, o);
    float a = __fdividef(e, sum);
    if (i < len) aw[w][i] = a;
    __syncwarp();

    int d = lane;
    float acc = 0.f;
    for (int j = 0; j < len; j++) {
        float mj = (j < 12) ? (float)(t - 1) : (float)(t - j + 12);
        acc += aw[w][j] * (Vb[w][j][d] + mj * Vpe[j * 128 + w * 32 + d]);
    }
    O[(size_t)bn * 128 + w * 32 + d] = rnd_tf32(acc);
}

// ---------------- host orchestration ----------------
static inline float* symaddr(const void* sym) {
    void* p = nullptr;
    cudaGetSymbolAddress(&p, sym);
    return (float*)p;
}
static inline __half* symaddr_h(const void* sym) {
    void* p = nullptr;
    cudaGetSymbolAddress(&p, sym);
    return (__half*)p;
}

template <int MODE, int APERM>
static inline void launch_gemm(cudaStream_t st,
                               const float* A, const float* W, const float* b, float* C,
                               int M, int N, int pos = 0,
                               __half* Kc = nullptr, __half* Vc = nullptr,
                               float* extra = nullptr, const float* Xg = nullptr,
                               const float* gam = nullptr, const float* bet = nullptr) {
    gemm3<MODE, APERM><<<dim3(N / 128, M / 128, 1), 256, GSMEM_BYTES, st>>>(
        A, W, b, C, A, W, b, C, M, N, pos, Kc, Vc, extra, Xg, gam, bet);
}

extern "C" void kernel_launch(void* const* d_in, const int* in_sizes, int n_in,
                              void* d_out, int out_size) {
    const float* X          = (const float*)d_in[0];
    const float* gru_w_ih   = (const float*)d_in[1];
    const float* gru_w_hh   = (const float*)d_in[2];
    const float* gru_b_ih   = (const float*)d_in[3];
    const float* gru_b_hh   = (const float*)d_in[4];
    const float* attn_in_w  = (const float*)d_in[5];
    const float* attn_in_b  = (const float*)d_in[6];
    const float* attn_out_w = (const float*)d_in[7];
    const float* attn_out_b = (const float*)d_in[8];
    const float* backcast_w = (const float*)d_in[9];
    const float* backcast_b = (const float*)d_in[10];
    const float* forecast_w = (const float*)d_in[11];
    const float* forecast_b = (const float*)d_in[12];
    const float* ln_gamma   = (const float*)d_in[13];
    const float* ln_beta    = (const float*)d_in[14];

    float* out  = (float*)d_out;
    float* res  = out;
    float* fore = out + RES_ELEMS;

    float*  GI    = symaddr(g_GI);
    float*  GH    = symaddr(g_GH);
    float*  rnn   = symaddr(g_rnn);
    float*  rnnpe = symaddr(g_rnnpe);
    float*  QKV   = symaddr(g_QKV);
    float*  attn  = symaddr(g_attn);
    float*  Z0    = symaddr(g_Z0);
    __half* Kc    = symaddr_h(g_Kc);
    __half* Vc    = symaddr_h(g_Vc);
    float*  pred  = symaddr(g_pred);
    float*  aresT = symaddr(g_aresT);
    float*  Qbuf  = symaddr(g_Qbuf);
    float*  GIdec = symaddr(g_GIdec);
    float*  GHdec = symaddr(g_GHdec);
    float*  gbuf  = symaddr(g_g);
    float*  hlast = symaddr(g_hlast);
    float*  pe    = symaddr(g_pe);
    float*  Kpe   = symaddr(g_Kpe);
    float*  Vpe   = symaddr(g_Vpe);
    float*  wih_r   = symaddr(g_wih_r);
    float*  whh_r   = symaddr(g_whh_r);
    float*  inw_r   = symaddr(g_inw_r);
    float*  outw_r  = symaddr(g_outw_r);
    float*  backw_r = symaddr(g_backw_r);
    float*  forew_r = symaddr(g_forew_r);
    float*  Wf      = symaddr(g_Wf);
    float*  bf      = symaddr(g_bf);

    static bool inited = false;
    static cudaStream_t s2 = 0;
    static cudaEvent_t evF = 0, evB1 = 0, evM1 = 0, evB2 = 0;
    if (!inited) {
        cudaFuncSetAttribute(gemm3<0,0>, cudaFuncAttributeMaxDynamicSharedMemorySize, GSMEM_BYTES);
        cudaFuncSetAttribute(gemm3<0,1>, cudaFuncAttributeMaxDynamicSharedMemorySize, GSMEM_BYTES);
        cudaFuncSetAttribute(gemm3<1,0>, cudaFuncAttributeMaxDynamicSharedMemorySize, GSMEM_BYTES);
        cudaFuncSetAttribute(gemm3<2,0>, cudaFuncAttributeMaxDynamicSharedMemorySize, GSMEM_BYTES);
        cudaFuncSetAttribute(gemm3<3,0>, cudaFuncAttributeMaxDynamicSharedMemorySize, GSMEM_BYTES);
        cudaFuncSetAttribute(gemm3<4,0>, cudaFuncAttributeMaxDynamicSharedMemorySize, GSMEM_BYTES);
        cudaFuncSetAttribute(gemm3<5,0>, cudaFuncAttributeMaxDynamicSharedMemorySize, GSMEM_BYTES);
        cudaFuncSetAttribute(gemm3<6,0>, cudaFuncAttributeMaxDynamicSharedMemorySize, GSMEM_BYTES);
        cudaStreamCreateWithFlags(&s2, cudaStreamNonBlocking);
        cudaEventCreateWithFlags(&evF,  cudaEventDisableTiming);
        cudaEventCreateWithFlags(&evB1, cudaEventDisableTiming);
        cudaEventCreateWithFlags(&evM1, cudaEventDisableTiming);
        cudaEventCreateWithFlags(&evB2, cudaEventDisableTiming);
        inited = true;
    }

    const int TPB = 256;
    const cudaStream_t s0 = 0;

    // ---- main prep ----
    pe_init_kernel<<<(64 * 128 + TPB - 1) / TPB, TPB, 0, s0>>>(pe);
    roundw_a_kernel<<<(147456 + TPB - 1) / TPB, TPB, 0, s0>>>(gru_w_ih, gru_w_hh, attn_in_w,
                                                              wih_r, whh_r, inw_r);
    cudaEventRecord(evF, s0);

    // ---- side stream: secondary prep (overlaps encoder) ----
    cudaStreamWaitEvent(s2, evF, 0);
    roundw_b_kernel<<<(65536 + TPB - 1) / TPB, TPB, 0, s2>>>(attn_out_w, backcast_w, forecast_w,
                                                             outw_r, backw_r, forew_r);
    wf_build_kernel<<<(49152 + TPB - 1) / TPB, TPB, 0, s2>>>(gru_w_ih, attn_out_w, attn_out_b,
                                                             gru_b_ih, Wf, bf);
    kvpe_kernel<<<(24 * 256 + TPB - 1) / TPB, TPB, 0, s2>>>(attn_in_w, pe, Kpe, Vpe);
    cudaEventRecord(evB1, s2);

    // ---- main: GI for all encoder steps (A read straight from X via row remap) ----
    launch_gemm<0, 1>(s0, X, wih_r, gru_b_ih, GI, LBN_, 384);

    // ---- GRU encode: step 0 gates-only, then 11x (GH gemm + gates) ----
    gru_gates_kernel<<<BN_ * 128 / TPB, TPB, 0, s0>>>(GI, nullptr, nullptr,
                                                      rnn, rnnpe, pe, gru_b_hh, BN_ * 128);
    for (int l = 1; l < 12; l++) {
        launch_gemm<0, 0>(s0, rnn + (size_t)(l - 1) * BN_ * 128, whh_r, gru_b_hh, GH, BN_, 384);
        gru_gates_kernel<<<BN_ * 128 / TPB, TPB, 0, s0>>>(GI + (size_t)l * BN_ * 384, GH,
                                                          rnn + (size_t)(l - 1) * BN_ * 128,
                                                          rnn + (size_t)l * BN_ * 128,
                                                          rnnpe + (size_t)l * BN_ * 128,
                                                          pe + l * 128, nullptr, BN_ * 128);
    }

    // ---- encoder MHA (QKV gemm scatters fp16 K/V into caches) ----
    launch_gemm<3, 0>(s0, rnnpe, inw_r, attn_in_b, QKV, LBN_, 384, 0, Kc, Vc);
    enc_attn_kernel<<<BN_, 128, 0, s0>>>(QKV, attn);
    cudaEventRecord(evM1, s0);

    // ---- side stream: backcast branch (overlaps decode loop) ----
    cudaStreamWaitEvent(s2, evM1, 0);
    launch_gemm<5, 0>(s2, attn, outw_r, attn_out_b, Z0, LBN_, 128, 0, nullptr, nullptr, pred);
    launch_gemm<6, 0>(s2, Z0, backw_r, backcast_b, res, LBN_, 128, 0, nullptr, nullptr,
                      nullptr, X, ln_gamma, ln_beta);
    cudaEventRecord(evB2, s2);

    // ---- main: decode loop (needs Wf/Kpe/Vpe from side stream part 1) ----
    cudaStreamWaitEvent(s0, evB1, 0);
    const float* hl = rnn + (size_t)11 * BN_ * 128;
    for (int t = 1; t <= 11; t++) {
        const float* prevA = (t == 1) ? attn + (size_t)11 * BN_ * 128
                                      : aresT + (size_t)(t - 2) * BN_ * 128;
        // fused pair: GIdec = prevA @ Wf^T + bf ; GHdec = hl @ w_hh^T + b_hh
        gemm3<0, 0><<<dim3(3, BN_ / 128, 2), 256, GSMEM_BYTES, s0>>>(
            prevA, Wf, bf, GIdec, hl, whh_r, gru_b_hh, GHdec,
            BN_, 384, 0, nullptr, nullptr, nullptr, nullptr, nullptr, nullptr);
        gru_gates_kernel<<<BN_ * 128 / TPB, TPB, 0, s0>>>(GIdec, GHdec, hl, gbuf,
                                                          hlast, pe + (11 + t) * 128,
                                                          nullptr, BN_ * 128);
        hl = hlast;
        launch_gemm<4, 0>(s0, gbuf, inw_r, attn_in_b, Qbuf, BN_, 384, 11 + t, Kc, Vc);
        dec_attn_kernel<<<BN_, 128, 0, s0>>>(Qbuf, Kc, Vc, Kpe, Vpe,
                                             aresT + (size_t)(t - 1) * BN_ * 128, t);
    }

    // ---- join side stream, then final output GEMMs ----
    cudaStreamWaitEvent(s0, evB2, 0);
    launch_gemm<1, 0>(s0, aresT, outw_r, attn_out_b, pred + (size_t)BN_ * 128, 11 * BN_, 128);
    launch_gemm<2, 0>(s0, pred, forew_r, forecast_b, fore, LBN_, 256);
}